// round 14
// baseline (speedup 1.0000x reference)
#include <cuda_runtime.h>
#include <cuda_fp16.h>
#include <cstdint>
#include <math.h>

#define NTOK 4096
#define EDIM 1024
#define CDIM 1024
#define HDIM 4096
#define VDIM 32000
#define EPS_LN 1e-5f

// ---------------------------------------------------------------------------
// Static scratch
// ---------------------------------------------------------------------------
__device__ float g_x[NTOK * EDIM];
__device__ float g_ctx[NTOK * CDIM];
__device__ float g_dl[NTOK * CDIM];
__device__ float g_ig[NTOK * CDIM];

// activation ping-pong buffers, fp16
__device__ __half g_act0[NTOK * HDIM];
__device__ __half g_act1[NTOK * HDIM];

// transposed weights [N,K], fp16 (7 live jobs)
#define WT_TOTAL 193986560ULL
__device__ __half g_wt[WT_TOTAL];

// ---------------------------------------------------------------------------
// helpers
// ---------------------------------------------------------------------------
__device__ __forceinline__ uint32_t smem_to_u32(const void* p) {
    uint32_t a;
    asm("{ .reg .u64 t; cvta.to.shared.u64 t, %1; cvt.u32.u64 %0, t; }"
        : "=r"(a) : "l"(p));
    return a;
}
__device__ __forceinline__ uint32_t swz(uint32_t o) { return o ^ ((o >> 3) & 0x70); }
__device__ __forceinline__ void cp_async16(uint32_t dst, const void* src) {
    asm volatile("cp.async.cg.shared.global [%0], [%1], 16;" :: "r"(dst), "l"(src));
}
template <int N>
__device__ __forceinline__ void cp_wait() {
    asm volatile("cp.async.wait_group %0;" :: "n"(N) : "memory");
}
__device__ __forceinline__ void cp_commit() {
    asm volatile("cp.async.commit_group;" ::: "memory");
}
__device__ __forceinline__ void ldsm_x4(uint32_t& a0, uint32_t& a1, uint32_t& a2,
                                        uint32_t& a3, uint32_t addr) {
    asm volatile("ldmatrix.sync.aligned.m8n8.x4.shared.b16 {%0,%1,%2,%3}, [%4];"
                 : "=r"(a0), "=r"(a1), "=r"(a2), "=r"(a3) : "r"(addr));
}
// fp16 MMA, fp32 accumulators
__device__ __forceinline__ void mma_f16(float& d0, float& d1, float& d2, float& d3,
                                        uint32_t a0, uint32_t a1, uint32_t a2, uint32_t a3,
                                        uint32_t b0, uint32_t b1) {
    asm volatile(
        "mma.sync.aligned.m16n8k16.row.col.f32.f16.f16.f32 "
        "{%0,%1,%2,%3}, {%4,%5,%6,%7}, {%8,%9}, {%0,%1,%2,%3};"
        : "+f"(d0), "+f"(d1), "+f"(d2), "+f"(d3)
        : "r"(a0), "r"(a1), "r"(a2), "r"(a3), "r"(b0), "r"(b1));
}

// ---------------------------------------------------------------------------
// block reductions (256 threads)
// ---------------------------------------------------------------------------
__device__ __forceinline__ float block_sum256(float val) {
    __shared__ float sh[8];
    int lane = threadIdx.x & 31;
    #pragma unroll
    for (int o = 16; o > 0; o >>= 1) val += __shfl_xor_sync(0xffffffffu, val, o);
    if (lane == 0) sh[threadIdx.x >> 5] = val;
    __syncthreads();
    float t = (lane < 8) ? sh[lane] : 0.f;
    #pragma unroll
    for (int o = 4; o > 0; o >>= 1) t += __shfl_xor_sync(0xffffffffu, t, o);
    t = __shfl_sync(0xffffffffu, t, 0);
    __syncthreads();
    return t;
}

// ---------------------------------------------------------------------------
// small kernels
// ---------------------------------------------------------------------------
__global__ void embed_ln_kernel(const int* __restrict__ ids,
                                const float* __restrict__ tbl,
                                const float* __restrict__ gw,
                                const float* __restrict__ gb) {
    int row = blockIdx.x;
    size_t base = (size_t)ids[row] * EDIM;
    float v[4];
    float s = 0.f;
    #pragma unroll
    for (int i = 0; i < 4; i++) { v[i] = tbl[base + threadIdx.x + i * 256]; s += v[i]; }
    float mean = block_sum256(s) * (1.f / (float)EDIM);
    float s2 = 0.f;
    #pragma unroll
    for (int i = 0; i < 4; i++) { float d = v[i] - mean; s2 += d * d; }
    float rstd = rsqrtf(block_sum256(s2) * (1.f / (float)EDIM) + EPS_LN);
    #pragma unroll
    for (int i = 0; i < 4; i++) {
        int c = threadIdx.x + i * 256;
        g_x[(size_t)row * EDIM + c] = (v[i] - mean) * rstd * gw[c] + gb[c];
    }
}

// ctx = LN(i*delta) for block 0 (ctx starts at zero -> f-gate term vanishes)
__global__ void ctx_update_kernel(const float* __restrict__ cg,
                                  const float* __restrict__ cb) {
    int row = blockIdx.x;
    size_t b = (size_t)row * CDIM;
    float v[4];
    float s = 0.f;
    #pragma unroll
    for (int i = 0; i < 4; i++) {
        int c = threadIdx.x + i * 256;
        v[i] = g_ig[b + c] * g_dl[b + c];
        s += v[i];
    }
    float mean = block_sum256(s) * (1.f / (float)CDIM);
    float s2 = 0.f;
    #pragma unroll
    for (int i = 0; i < 4; i++) { float d = v[i] - mean; s2 += d * d; }
    float rstd = rsqrtf(block_sum256(s2) * (1.f / (float)CDIM) + EPS_LN);
    #pragma unroll
    for (int i = 0; i < 4; i++) {
        int c = threadIdx.x + i * 256;
        g_ctx[b + c] = (v[i] - mean) * rstd * cg[c] + cb[c];
    }
}

// cat = [x | (first ? 0 : ctx)] -> fp16, row stride 2048
__global__ void cat_half_kernel(int first, __half* __restrict__ dst) {
    int idx = blockIdx.x * blockDim.x + threadIdx.x;
    int row = idx >> 9, c4 = idx & 511;
    float4 v;
    if (c4 < 256)      v = ((const float4*)g_x)[row * 256 + c4];
    else if (first)    v = make_float4(0.f, 0.f, 0.f, 0.f);
    else               v = ((const float4*)g_ctx)[row * 256 + (c4 - 256)];
    __half2 h0 = __floats2half2_rn(v.x, v.y);
    __half2 h1 = __floats2half2_rn(v.z, v.w);
    *(uint2*)(dst + (size_t)row * 2048 + c4 * 4) =
        make_uint2(*(uint32_t*)&h0, *(uint32_t*)&h1);
}

// ---------------------------------------------------------------------------
// Fused weight conversion: 7 live jobs, W[K,N] fp32 -> Wt[N,K] fp16
// (dw0 and iw0 contiguous -> one [2048,K] gate matrix)
// ---------------------------------------------------------------------------
#define NJOB 7
struct WJobs {
    const float* W[NJOB];
    long long off[NJOB];
    int K[NJOB];
    int N[NJOB];
    int start[NJOB + 1];
};

__global__ void wsplit_all_kernel(WJobs jobs, __half* __restrict__ T) {
    __shared__ float t[32][33];
    int b = blockIdx.x;
    int ji = 0;
    #pragma unroll
    for (int j = 0; j < NJOB; j++) if (b >= jobs.start[j + 1]) ji = j + 1;
    const float* W = jobs.W[ji];
    const int K = jobs.K[ji], N = jobs.N[ji];
    const long long off = jobs.off[ji];
    int tno = b - jobs.start[ji];
    int ntiles = N >> 5;
    int n0 = (tno % ntiles) << 5, k0 = (tno / ntiles) << 5;
    int tx = threadIdx.x & 31, ty = threadIdx.x >> 5;
    #pragma unroll
    for (int i = 0; i < 4; i++) {
        int kk = ty + i * 8;
        t[kk][tx] = W[(size_t)(k0 + kk) * N + n0 + tx];
    }
    __syncthreads();
    #pragma unroll
    for (int i = 0; i < 4; i++) {
        int nn = ty + i * 8;
        T[(size_t)off + (size_t)(n0 + nn) * K + k0 + tx] = __float2half(t[tx][nn]);
    }
}

// ---------------------------------------------------------------------------
// fp16 GEMM (single-pass): C[M,N] = act(A @ W^T + bias)
// Block tile 64x128, BK=64. 128 threads = 4 warps (2m x 2n), warp 32x64.
// Stage: A(8K)|B(16K) = 24KB; 3-stage pipeline = 72KB -> 3 CTAs/SM.
// One __syncthreads per k-tile.
// EPI: 0 none->f32, 1 relu->f16, 4 gate-pair (tanh | sigmoid, stride 1024).
// ---------------------------------------------------------------------------
#define STAGE_BYTES 24576
#define OFF_B 8192
#define GEMM_SMEM (3 * STAGE_BYTES)

template <int EPI, int SPLIT>
__global__ void __launch_bounds__(128, 3)
gemm_f16(const __half* __restrict__ aIn, const __half* __restrict__ bW,
         const float* __restrict__ bias, const float* __restrict__ bias2,
         float* __restrict__ outF, float* __restrict__ outF2,
         __half* __restrict__ outH,
         int N, int K) {
    extern __shared__ char smem[];
    const uint32_t sbase = smem_to_u32(smem);
    const int tid = threadIdx.x, wid = tid >> 5, lane = tid & 31;
    const int warp_m = wid & 1, warp_n = wid >> 1;   // 2m x 2n
    const int rowBase = blockIdx.x * 64;
    const int colBase = blockIdx.y * 128;

    float acc[2][8][4];
    #pragma unroll
    for (int i = 0; i < 2; i++)
        #pragma unroll
        for (int j = 0; j < 8; j++)
            #pragma unroll
            for (int u = 0; u < 4; u++) acc[i][j][u] = 0.f;

    const int nk = K >> 6;

    // ldmatrix lane addressing
    const int aRow = warp_m * 32 + (lane & 15);                      // + i*16
    const int aByte = (lane >> 4) << 4;                              // 0/16
    const int bRow = warp_n * 64 + ((lane >> 4) << 3) + (lane & 7);  // + jj*16
    const int bByte = ((lane >> 3) & 1) << 4;                        // 0/16

    auto fill = [&](int kt) {
        const uint32_t st = sbase + (kt % 3) * STAGE_BYTES;
        const int k0 = kt << 6;
        #pragma unroll
        for (int i = 0; i < 12; i++) {
            int o = tid + (i << 7);
            const __half* src;
            uint32_t dst;
            if (o < 512) {
                int r = o >> 3, c = o & 7;
                src = aIn + (size_t)(rowBase + r) * K + k0 + c * 8;
                dst = st + swz(r * 128 + c * 16);
            } else {
                int q = o - 512, r = q >> 3, c = q & 7;
                src = bW + (size_t)(colBase + r) * K + k0 + c * 8;
                dst = st + OFF_B + swz(r * 128 + c * 16);
            }
            cp_async16(dst, src);
        }
        cp_commit();
    };

    fill(0);
    fill(1);
    for (int kt = 0; kt < nk; kt++) {
        if (kt + 1 < nk) cp_wait<1>();
        else             cp_wait<0>();
        __syncthreads();
        if (kt + 2 < nk) fill(kt + 2);

        const uint32_t st = sbase + (kt % 3) * STAGE_BYTES;
        #pragma unroll
        for (int ks = 0; ks < 4; ks++) {
            uint32_t af[2][4], bf[8][2];
            #pragma unroll
            for (int i = 0; i < 2; i++)
                ldsm_x4(af[i][0], af[i][1], af[i][2], af[i][3],
                        st + swz((aRow + i * 16) * 128 + ks * 32 + aByte));
            #pragma unroll
            for (int jj = 0; jj < 4; jj++)
                ldsm_x4(bf[2*jj][0], bf[2*jj][1], bf[2*jj+1][0], bf[2*jj+1][1],
                        st + OFF_B + swz((bRow + jj * 16) * 128 + ks * 32 + bByte));
            #pragma unroll
            for (int i = 0; i < 2; i++)
                #pragma unroll
                for (int j = 0; j < 8; j++)
                    mma_f16(acc[i][j][0], acc[i][j][1], acc[i][j][2], acc[i][j][3],
                            af[i][0], af[i][1], af[i][2], af[i][3], bf[j][0], bf[j][1]);
        }
        // single barrier per k-tile (refill target ordered by this barrier)
        __syncthreads();
    }

    // epilogue
    const int erow = rowBase + warp_m * 32 + (lane >> 2);
    const int ecol = colBase + warp_n * 64 + (lane & 3) * 2;
    #pragma unroll
    for (int i = 0; i < 2; i++) {
        #pragma unroll
        for (int j = 0; j < 8; j++) {
            int col = ecol + j * 8;
            #pragma unroll
            for (int h = 0; h < 2; h++) {
                int r = erow + i * 16 + h * 8;
                float a0 = acc[i][j][2 * h + 0];
                float a1 = acc[i][j][2 * h + 1];
                if (EPI == 4) {
                    bool lo = col < 1024;
                    const float* bs = lo ? bias : bias2;
                    float* op = lo ? outF : outF2;
                    int cc = lo ? col : col - 1024;
                    float x0 = a0 + bs[cc], x1 = a1 + bs[cc + 1];
                    if (lo) { x0 = tanhf(x0); x1 = tanhf(x1); }
                    else    { x0 = 1.f / (1.f + expf(-x0)); x1 = 1.f / (1.f + expf(-x1)); }
                    *(float2*)(op + (size_t)r * 1024 + cc) = make_float2(x0, x1);
                } else {
                    float x0 = a0 + bias[col], x1 = a1 + bias[col + 1];
                    if (EPI == 1) { x0 = fmaxf(x0, 0.f); x1 = fmaxf(x1, 0.f); }
                    if (SPLIT == 0) {
                        *(float2*)(outF + (size_t)r * N + col) = make_float2(x0, x1);
                    } else {
                        __half2 hv = __floats2half2_rn(x0, x1);
                        *(uint32_t*)(outH + (size_t)r * N + col) = *(uint32_t*)&hv;
                    }
                }
            }
        }
    }
}

// ---------------------------------------------------------------------------
// Launch
// ---------------------------------------------------------------------------
extern "C" void kernel_launch(void* const* d_in, const int* in_sizes, int n_in,
                              void* d_out, int out_size) {
    (void)in_sizes; (void)n_in; (void)out_size;

    const int*   ids  = (const int*)d_in[0];
    const float* tbl  = (const float*)d_in[1];
    const float* en_g = (const float*)d_in[2];
    const float* en_b = (const float*)d_in[3];
    const float* wA[2] = {(const float*)d_in[4],  (const float*)d_in[8]};
    const float* bA[2] = {(const float*)d_in[5],  (const float*)d_in[9]};
    const float* wB[2] = {(const float*)d_in[6],  (const float*)d_in[10]};
    const float* bB[2] = {(const float*)d_in[7],  (const float*)d_in[11]};
    const float* dw0 = (const float*)d_in[12];
    const float* db0 = (const float*)d_in[13];
    const float* iw0 = (const float*)d_in[16];
    const float* ib0 = (const float*)d_in[17];
    const float* cg0 = (const float*)d_in[18];
    const float* cb0 = (const float*)d_in[19];
    const float* ow = (const float*)d_in[28];
    const float* ob = (const float*)d_in[29];
    float* out = (float*)d_out;

    float *pdl, *pig;
    __half *act[2], *wt;
    cudaGetSymbolAddress((void**)&pdl,    g_dl);
    cudaGetSymbolAddress((void**)&pig,    g_ig);
    cudaGetSymbolAddress((void**)&act[0], g_act0);
    cudaGetSymbolAddress((void**)&act[1], g_act1);
    cudaGetSymbolAddress((void**)&wt,     g_wt);

    cudaFuncSetAttribute(gemm_f16<1, 1>, cudaFuncAttributeMaxDynamicSharedMemorySize, GEMM_SMEM);
    cudaFuncSetAttribute(gemm_f16<4, 0>, cudaFuncAttributeMaxDynamicSharedMemorySize, GEMM_SMEM);
    cudaFuncSetAttribute(gemm_f16<0, 0>, cudaFuncAttributeMaxDynamicSharedMemorySize, GEMM_SMEM);

    // weight arena offsets (elements): wA0 wB0 dw0 iw0 wA1 wB1 ow
    const long long EO_WA[2] = {0, 33554432};
    const long long EO_WB[2] = {8388608, 41943040};
    const long long EO_GATE = 25165824;            // dw0 | iw0 contiguous
    const long long EO_OW = 58720256;

    {
        WJobs jobs;
        const float* ws[NJOB] = {wA[0], wB[0], dw0, iw0, wA[1], wB[1], ow};
        const long long eo[NJOB] = {EO_WA[0], EO_WB[0], EO_GATE, EO_GATE + 4194304,
                                    EO_WA[1], EO_WB[1], EO_OW};
        const int Ks[NJOB] = {2048, 4096, 4096, 4096, 2048, 4096, 4096};
        const int Ns[NJOB] = {4096, 4096, 1024, 1024, 4096, 4096, 32000};
        int cum = 0;
        for (int j = 0; j < NJOB; j++) {
            jobs.W[j] = ws[j]; jobs.off[j] = eo[j];
            jobs.K[j] = Ks[j]; jobs.N[j] = Ns[j];
            jobs.start[j] = cum;
            cum += (Ns[j] >> 5) * (Ks[j] >> 5);
        }
        jobs.start[NJOB] = cum;
        wsplit_all_kernel<<<cum, 256>>>(jobs, wt);
    }

    embed_ln_kernel<<<NTOK, 256>>>(ids, tbl, en_g, en_b);

    for (int blk = 0; blk < 2; blk++) {
        int p = blk & 1;
        int q = 1 - p;
        cat_half_kernel<<<NTOK * 2048 / 4 / 256, 256>>>(blk == 0 ? 1 : 0, act[p]);
        // h1 = relu(cat @ wA + bA) -> fp16
        gemm_f16<1, 1><<<dim3(NTOK / 64, HDIM / 128), 128, GEMM_SMEM>>>(
            act[p], wt + EO_WA[blk], bA[blk], nullptr,
            nullptr, nullptr, act[q], HDIM, EDIM + CDIM);
        // h2 = relu(h1 @ wB + bB) -> fp16
        gemm_f16<1, 1><<<dim3(NTOK / 64, HDIM / 128), 128, GEMM_SMEM>>>(
            act[q], wt + EO_WB[blk], bB[blk], nullptr,
            nullptr, nullptr, act[p], HDIM, HDIM);
        if (blk == 0) {
            // merged gates: N=2048 (delta|i), epilogue splits tanh/sigmoid
            gemm_f16<4, 0><<<dim3(NTOK / 64, 2048 / 128), 128, GEMM_SMEM>>>(
                act[p], wt + EO_GATE, db0, ib0,
                pdl, pig, nullptr, 2048, HDIM);
            ctx_update_kernel<<<NTOK, 256>>>(cg0, cb0);
        }
    }

    // logits = h2(block 1) @ ow + ob
    gemm_f16<0, 0><<<dim3(NTOK / 64, VDIM / 128), 128, GEMM_SMEM>>>(
        act[1], wt + EO_OW, ob, nullptr,
        out, nullptr, nullptr, VDIM, HDIM);
}

// round 15
// speedup vs baseline: 1.0242x; 1.0242x over previous
#include <cuda_runtime.h>
#include <cuda_fp16.h>
#include <cstdint>
#include <math.h>

#define NTOK 4096
#define EDIM 1024
#define CDIM 1024
#define HDIM 4096
#define VDIM 32000
#define EPS_LN 1e-5f

// ---------------------------------------------------------------------------
// Static scratch
// ---------------------------------------------------------------------------
__device__ float g_x[NTOK * EDIM];
__device__ float g_ctx[NTOK * CDIM];
__device__ float g_dl[NTOK * CDIM];
__device__ float g_ig[NTOK * CDIM];

__device__ __half g_act0[NTOK * HDIM];
__device__ __half g_act1[NTOK * HDIM];

#define WT_TOTAL 193986560ULL
__device__ __half g_wt[WT_TOTAL];

// ---------------------------------------------------------------------------
// helpers
// ---------------------------------------------------------------------------
__device__ __forceinline__ uint32_t smem_to_u32(const void* p) {
    uint32_t a;
    asm("{ .reg .u64 t; cvta.to.shared.u64 t, %1; cvt.u32.u64 %0, t; }"
        : "=r"(a) : "l"(p));
    return a;
}
__device__ __forceinline__ uint32_t swz(uint32_t o) { return o ^ ((o >> 3) & 0x70); }
__device__ __forceinline__ void cp_async16(uint32_t dst, const void* src) {
    asm volatile("cp.async.cg.shared.global [%0], [%1], 16;" :: "r"(dst), "l"(src));
}
__device__ __forceinline__ void ldsm_x4(uint32_t& a0, uint32_t& a1, uint32_t& a2,
                                        uint32_t& a3, uint32_t addr) {
    asm volatile("ldmatrix.sync.aligned.m8n8.x4.shared.b16 {%0,%1,%2,%3}, [%4];"
                 : "=r"(a0), "=r"(a1), "=r"(a2), "=r"(a3) : "r"(addr));
}
__device__ __forceinline__ void mma_f16(float& d0, float& d1, float& d2, float& d3,
                                        uint32_t a0, uint32_t a1, uint32_t a2, uint32_t a3,
                                        uint32_t b0, uint32_t b1) {
    asm volatile(
        "mma.sync.aligned.m16n8k16.row.col.f32.f16.f16.f32 "
        "{%0,%1,%2,%3}, {%4,%5,%6,%7}, {%8,%9}, {%0,%1,%2,%3};"
        : "+f"(d0), "+f"(d1), "+f"(d2), "+f"(d3)
        : "r"(a0), "r"(a1), "r"(a2), "r"(a3), "r"(b0), "r"(b1));
}

// ---- mbarrier primitives (sm_80/90 PTX; compiled OK under compute_103) ----
__device__ __forceinline__ void mbar_init(uint32_t addr, uint32_t cnt) {
    asm volatile("mbarrier.init.shared.b64 [%0], %1;" :: "r"(addr), "r"(cnt) : "memory");
}
__device__ __forceinline__ void mbar_arrive(uint32_t addr) {
    asm volatile("mbarrier.arrive.shared.b64 _, [%0];" :: "r"(addr) : "memory");
}
__device__ __forceinline__ void cp_async_mbar_arrive(uint32_t addr) {
    asm volatile("cp.async.mbarrier.arrive.noinc.shared.b64 [%0];" :: "r"(addr) : "memory");
}
__device__ __forceinline__ void mbar_wait(uint32_t addr, uint32_t parity) {
    uint32_t done;
    asm volatile(
        "{\n\t.reg .pred p;\n\t"
        "mbarrier.try_wait.parity.acquire.cta.shared::cta.b64 p, [%1], %2;\n\t"
        "selp.b32 %0, 1, 0, p;\n\t}"
        : "=r"(done) : "r"(addr), "r"(parity) : "memory");
    if (!done) {
        asm volatile(
            "{\n\t.reg .pred P1;\n\t"
            "WL_%=:\n\t"
            "mbarrier.try_wait.parity.acquire.cta.shared::cta.b64 P1, [%0], %1, 0x989680;\n\t"
            "@P1 bra.uni WD_%=;\n\t"
            "bra.uni WL_%=;\n\t"
            "WD_%=:\n\t}"
            :: "r"(addr), "r"(parity) : "memory");
    }
}

// ---------------------------------------------------------------------------
// block reductions (256 threads)
// ---------------------------------------------------------------------------
__device__ __forceinline__ float block_sum256(float val) {
    __shared__ float sh[8];
    int lane = threadIdx.x & 31;
    #pragma unroll
    for (int o = 16; o > 0; o >>= 1) val += __shfl_xor_sync(0xffffffffu, val, o);
    if (lane == 0) sh[threadIdx.x >> 5] = val;
    __syncthreads();
    float t = (lane < 8) ? sh[lane] : 0.f;
    #pragma unroll
    for (int o = 4; o > 0; o >>= 1) t += __shfl_xor_sync(0xffffffffu, t, o);
    t = __shfl_sync(0xffffffffu, t, 0);
    __syncthreads();
    return t;
}

// ---------------------------------------------------------------------------
// small kernels
// ---------------------------------------------------------------------------
__global__ void embed_ln_kernel(const int* __restrict__ ids,
                                const float* __restrict__ tbl,
                                const float* __restrict__ gw,
                                const float* __restrict__ gb) {
    int row = blockIdx.x;
    size_t base = (size_t)ids[row] * EDIM;
    float v[4];
    float s = 0.f;
    #pragma unroll
    for (int i = 0; i < 4; i++) { v[i] = tbl[base + threadIdx.x + i * 256]; s += v[i]; }
    float mean = block_sum256(s) * (1.f / (float)EDIM);
    float s2 = 0.f;
    #pragma unroll
    for (int i = 0; i < 4; i++) { float d = v[i] - mean; s2 += d * d; }
    float rstd = rsqrtf(block_sum256(s2) * (1.f / (float)EDIM) + EPS_LN);
    #pragma unroll
    for (int i = 0; i < 4; i++) {
        int c = threadIdx.x + i * 256;
        g_x[(size_t)row * EDIM + c] = (v[i] - mean) * rstd * gw[c] + gb[c];
    }
}

__global__ void ctx_update_kernel(const float* __restrict__ cg,
                                  const float* __restrict__ cb) {
    int row = blockIdx.x;
    size_t b = (size_t)row * CDIM;
    float v[4];
    float s = 0.f;
    #pragma unroll
    for (int i = 0; i < 4; i++) {
        int c = threadIdx.x + i * 256;
        v[i] = g_ig[b + c] * g_dl[b + c];
        s += v[i];
    }
    float mean = block_sum256(s) * (1.f / (float)CDIM);
    float s2 = 0.f;
    #pragma unroll
    for (int i = 0; i < 4; i++) { float d = v[i] - mean; s2 += d * d; }
    float rstd = rsqrtf(block_sum256(s2) * (1.f / (float)CDIM) + EPS_LN);
    #pragma unroll
    for (int i = 0; i < 4; i++) {
        int c = threadIdx.x + i * 256;
        g_ctx[b + c] = (v[i] - mean) * rstd * cg[c] + cb[c];
    }
}

__global__ void cat_half_kernel(int first, __half* __restrict__ dst) {
    int idx = blockIdx.x * blockDim.x + threadIdx.x;
    int row = idx >> 9, c4 = idx & 511;
    float4 v;
    if (c4 < 256)      v = ((const float4*)g_x)[row * 256 + c4];
    else if (first)    v = make_float4(0.f, 0.f, 0.f, 0.f);
    else               v = ((const float4*)g_ctx)[row * 256 + (c4 - 256)];
    __half2 h0 = __floats2half2_rn(v.x, v.y);
    __half2 h1 = __floats2half2_rn(v.z, v.w);
    *(uint2*)(dst + (size_t)row * 2048 + c4 * 4) =
        make_uint2(*(uint32_t*)&h0, *(uint32_t*)&h1);
}

// ---------------------------------------------------------------------------
// Fused weight conversion: 7 live jobs, W[K,N] fp32 -> Wt[N,K] fp16
// ---------------------------------------------------------------------------
#define NJOB 7
struct WJobs {
    const float* W[NJOB];
    long long off[NJOB];
    int K[NJOB];
    int N[NJOB];
    int start[NJOB + 1];
};

__global__ void wsplit_all_kernel(WJobs jobs, __half* __restrict__ T) {
    __shared__ float t[32][33];
    int b = blockIdx.x;
    int ji = 0;
    #pragma unroll
    for (int j = 0; j < NJOB; j++) if (b >= jobs.start[j + 1]) ji = j + 1;
    const float* W = jobs.W[ji];
    const int K = jobs.K[ji], N = jobs.N[ji];
    const long long off = jobs.off[ji];
    int tno = b - jobs.start[ji];
    int ntiles = N >> 5;
    int n0 = (tno % ntiles) << 5, k0 = (tno / ntiles) << 5;
    int tx = threadIdx.x & 31, ty = threadIdx.x >> 5;
    #pragma unroll
    for (int i = 0; i < 4; i++) {
        int kk = ty + i * 8;
        t[kk][tx] = W[(size_t)(k0 + kk) * N + n0 + tx];
    }
    __syncthreads();
    #pragma unroll
    for (int i = 0; i < 4; i++) {
        int nn = ty + i * 8;
        T[(size_t)off + (size_t)(n0 + nn) * K + k0 + tx] = __float2half(t[tx][nn]);
    }
}

// ---------------------------------------------------------------------------
// Warp-specialized fp16 GEMM: C[M,N] = act(A @ W^T + bias)
// 512 threads: warps 0-7 consumers (2m x 4n, warp 32x64, block 64x256),
//              warps 8-15 producers (all cp.async fills).
// 5-stage pipeline, stage = A(8K)|B(32K) = 40KB. NO __syncthreads in mainloop:
// consumers wait mbarrier full[s]; producers wait empty[s]. Consumer warps
// never wait on each other -> barrier skew fully absorbed.
// EPI: 0 none->f32, 1 relu->f16, 4 gate-pair (tanh | sigmoid, stride 1024).
// ---------------------------------------------------------------------------
#define NSTAGE 5
#define STAGE_BYTES 40960
#define OFF_B 8192
#define SM_DATA 1024
#define GEMM_SMEM (SM_DATA + NSTAGE * STAGE_BYTES)

template <int EPI, int SPLIT>
__global__ void __launch_bounds__(512, 1)
gemm_f16(const __half* __restrict__ aIn, const __half* __restrict__ bW,
         const float* __restrict__ bias, const float* __restrict__ bias2,
         float* __restrict__ outF, float* __restrict__ outF2,
         __half* __restrict__ outH,
         int N, int K) {
    extern __shared__ char smem[];
    const uint32_t sbase = smem_to_u32(smem);
    const int tid = threadIdx.x, wid = tid >> 5, lane = tid & 31;
    const int rowBase = blockIdx.x * 64;
    const int colBase = blockIdx.y * 256;
    const int nk = K >> 6;

    // mbarriers: full[s] at sbase + s*8, empty[s] at sbase + 64 + s*8
    if (tid == 0) {
        #pragma unroll
        for (int s = 0; s < NSTAGE; s++) {
            mbar_init(sbase + s * 8, 256);        // full: 256 producer arrives
            mbar_init(sbase + 64 + s * 8, 256);   // empty: 256 consumer arrives
        }
    }
    __syncthreads();

    if (wid >= 8) {
        // ---------------- producer ----------------
        const int ptid = tid - 256;   // 0..255
        auto fill = [&](int kt, int s) {
            const uint32_t st = sbase + SM_DATA + s * STAGE_BYTES;
            const int k0 = kt << 6;
            #pragma unroll
            for (int i = 0; i < 10; i++) {
                int o = ptid + (i << 8);
                const __half* src;
                uint32_t dst;
                if (o < 512) {
                    int r = o >> 3, c = o & 7;
                    src = aIn + (size_t)(rowBase + r) * K + k0 + c * 8;
                    dst = st + swz(r * 128 + c * 16);
                } else {
                    int q = o - 512, r = q >> 3, c = q & 7;
                    src = bW + (size_t)(colBase + r) * K + k0 + c * 8;
                    dst = st + OFF_B + swz(r * 128 + c * 16);
                }
                cp_async16(dst, src);
            }
            cp_async_mbar_arrive(sbase + s * 8);
        };
        int pe0 = 0, pe1 = 0, pe2 = 0, pe3 = 0, pe4 = 0;
        for (int kt = 0; kt < nk; kt += NSTAGE) {
            if (kt >= NSTAGE) { mbar_wait(sbase + 64 + 0 * 8, pe0); pe0 ^= 1; }
            fill(kt + 0, 0);
            if (kt + 1 < nk) {
                if (kt + 1 >= NSTAGE) { mbar_wait(sbase + 64 + 1 * 8, pe1); pe1 ^= 1; }
                fill(kt + 1, 1);
            }
            if (kt + 2 < nk) {
                if (kt + 2 >= NSTAGE) { mbar_wait(sbase + 64 + 2 * 8, pe2); pe2 ^= 1; }
                fill(kt + 2, 2);
            }
            if (kt + 3 < nk) {
                if (kt + 3 >= NSTAGE) { mbar_wait(sbase + 64 + 3 * 8, pe3); pe3 ^= 1; }
                fill(kt + 3, 3);
            }
            if (kt + 4 < nk) {
                if (kt + 4 >= NSTAGE) { mbar_wait(sbase + 64 + 4 * 8, pe4); pe4 ^= 1; }
                fill(kt + 4, 4);
            }
        }
        return;
    }

    // ---------------- consumer ----------------
    const int warp_m = wid & 1, warp_n = wid >> 1;   // 2m x 4n
    float acc[2][8][4];
    #pragma unroll
    for (int i = 0; i < 2; i++)
        #pragma unroll
        for (int j = 0; j < 8; j++)
            #pragma unroll
            for (int u = 0; u < 4; u++) acc[i][j][u] = 0.f;

    const int aRow = warp_m * 32 + (lane & 15);
    const int aByte = (lane >> 4) << 4;
    const int bRow = warp_n * 64 + ((lane >> 4) << 3) + (lane & 7);
    const int bByte = ((lane >> 3) & 1) << 4;

    auto compute = [&](int s) {
        const uint32_t st = sbase + SM_DATA + s * STAGE_BYTES;
        #pragma unroll
        for (int ks = 0; ks < 4; ks++) {
            uint32_t af[2][4], bf[8][2];
            #pragma unroll
            for (int i = 0; i < 2; i++)
                ldsm_x4(af[i][0], af[i][1], af[i][2], af[i][3],
                        st + swz((aRow + i * 16) * 128 + ks * 32 + aByte));
            #pragma unroll
            for (int jj = 0; jj < 4; jj++)
                ldsm_x4(bf[2*jj][0], bf[2*jj][1], bf[2*jj+1][0], bf[2*jj+1][1],
                        st + OFF_B + swz((bRow + jj * 16) * 128 + ks * 32 + bByte));
            #pragma unroll
            for (int i = 0; i < 2; i++)
                #pragma unroll
                for (int j = 0; j < 8; j++)
                    mma_f16(acc[i][j][0], acc[i][j][1], acc[i][j][2], acc[i][j][3],
                            af[i][0], af[i][1], af[i][2], af[i][3], bf[j][0], bf[j][1]);
        }
        mbar_arrive(sbase + 64 + s * 8);
    };

    int pf0 = 0, pf1 = 0, pf2 = 0, pf3 = 0, pf4 = 0;
    for (int kt = 0; kt < nk; kt += NSTAGE) {
        mbar_wait(sbase + 0 * 8, pf0); pf0 ^= 1; compute(0);
        if (kt + 1 < nk) { mbar_wait(sbase + 1 * 8, pf1); pf1 ^= 1; compute(1); }
        if (kt + 2 < nk) { mbar_wait(sbase + 2 * 8, pf2); pf2 ^= 1; compute(2); }
        if (kt + 3 < nk) { mbar_wait(sbase + 3 * 8, pf3); pf3 ^= 1; compute(3); }
        if (kt + 4 < nk) { mbar_wait(sbase + 4 * 8, pf4); pf4 ^= 1; compute(4); }
    }

    // epilogue (consumer warps only)
    const int erow = rowBase + warp_m * 32 + (lane >> 2);
    const int ecol = colBase + warp_n * 64 + (lane & 3) * 2;
    #pragma unroll
    for (int i = 0; i < 2; i++) {
        #pragma unroll
        for (int j = 0; j < 8; j++) {
            int col = ecol + j * 8;
            #pragma unroll
            for (int h = 0; h < 2; h++) {
                int r = erow + i * 16 + h * 8;
                float a0 = acc[i][j][2 * h + 0];
                float a1 = acc[i][j][2 * h + 1];
                if (EPI == 4) {
                    bool lo = col < 1024;
                    const float* bs = lo ? bias : bias2;
                    float* op = lo ? outF : outF2;
                    int cc = lo ? col : col - 1024;
                    float x0 = a0 + bs[cc], x1 = a1 + bs[cc + 1];
                    if (lo) { x0 = tanhf(x0); x1 = tanhf(x1); }
                    else    { x0 = 1.f / (1.f + expf(-x0)); x1 = 1.f / (1.f + expf(-x1)); }
                    *(float2*)(op + (size_t)r * 1024 + cc) = make_float2(x0, x1);
                } else {
                    float x0 = a0 + bias[col], x1 = a1 + bias[col + 1];
                    if (EPI == 1) { x0 = fmaxf(x0, 0.f); x1 = fmaxf(x1, 0.f); }
                    if (SPLIT == 0) {
                        *(float2*)(outF + (size_t)r * N + col) = make_float2(x0, x1);
                    } else {
                        __half2 hv = __floats2half2_rn(x0, x1);
                        *(uint32_t*)(outH + (size_t)r * N + col) = *(uint32_t*)&hv;
                    }
                }
            }
        }
    }
}

// ---------------------------------------------------------------------------
// Launch
// ---------------------------------------------------------------------------
extern "C" void kernel_launch(void* const* d_in, const int* in_sizes, int n_in,
                              void* d_out, int out_size) {
    (void)in_sizes; (void)n_in; (void)out_size;

    const int*   ids  = (const int*)d_in[0];
    const float* tbl  = (const float*)d_in[1];
    const float* en_g = (const float*)d_in[2];
    const float* en_b = (const float*)d_in[3];
    const float* wA[2] = {(const float*)d_in[4],  (const float*)d_in[8]};
    const float* bA[2] = {(const float*)d_in[5],  (const float*)d_in[9]};
    const float* wB[2] = {(const float*)d_in[6],  (const float*)d_in[10]};
    const float* bB[2] = {(const float*)d_in[7],  (const float*)d_in[11]};
    const float* dw0 = (const float*)d_in[12];
    const float* db0 = (const float*)d_in[13];
    const float* iw0 = (const float*)d_in[16];
    const float* ib0 = (const float*)d_in[17];
    const float* cg0 = (const float*)d_in[18];
    const float* cb0 = (const float*)d_in[19];
    const float* ow = (const float*)d_in[28];
    const float* ob = (const float*)d_in[29];
    float* out = (float*)d_out;

    float *pdl, *pig;
    __half *act[2], *wt;
    cudaGetSymbolAddress((void**)&pdl,    g_dl);
    cudaGetSymbolAddress((void**)&pig,    g_ig);
    cudaGetSymbolAddress((void**)&act[0], g_act0);
    cudaGetSymbolAddress((void**)&act[1], g_act1);
    cudaGetSymbolAddress((void**)&wt,     g_wt);

    cudaFuncSetAttribute(gemm_f16<1, 1>, cudaFuncAttributeMaxDynamicSharedMemorySize, GEMM_SMEM);
    cudaFuncSetAttribute(gemm_f16<4, 0>, cudaFuncAttributeMaxDynamicSharedMemorySize, GEMM_SMEM);
    cudaFuncSetAttribute(gemm_f16<0, 0>, cudaFuncAttributeMaxDynamicSharedMemorySize, GEMM_SMEM);

    // weight arena offsets (elements): wA0 wB0 dw0 iw0 wA1 wB1 ow
    const long long EO_WA[2] = {0, 33554432};
    const long long EO_WB[2] = {8388608, 41943040};
    const long long EO_GATE = 25165824;            // dw0 | iw0 contiguous
    const long long EO_OW = 58720256;

    {
        WJobs jobs;
        const float* ws[NJOB] = {wA[0], wB[0], dw0, iw0, wA[1], wB[1], ow};
        const long long eo[NJOB] = {EO_WA[0], EO_WB[0], EO_GATE, EO_GATE + 4194304,
                                    EO_WA[1], EO_WB[1], EO_OW};
        const int Ks[NJOB] = {2048, 4096, 4096, 4096, 2048, 4096, 4096};
        const int Ns[NJOB] = {4096, 4096, 1024, 1024, 4096, 4096, 32000};
        int cum = 0;
        for (int j = 0; j < NJOB; j++) {
            jobs.W[j] = ws[j]; jobs.off[j] = eo[j];
            jobs.K[j] = Ks[j]; jobs.N[j] = Ns[j];
            jobs.start[j] = cum;
            cum += (Ns[j] >> 5) * (Ks[j] >> 5);
        }
        jobs.start[NJOB] = cum;
        wsplit_all_kernel<<<cum, 256>>>(jobs, wt);
    }

    embed_ln_kernel<<<NTOK, 256>>>(ids, tbl, en_g, en_b);

    for (int blk = 0; blk < 2; blk++) {
        int p = blk & 1;
        int q = 1 - p;
        cat_half_kernel<<<NTOK * 2048 / 4 / 256, 256>>>(blk == 0 ? 1 : 0, act[p]);
        // h1 = relu(cat @ wA + bA) -> fp16
        gemm_f16<1, 1><<<dim3(NTOK / 64, HDIM / 256), 512, GEMM_SMEM>>>(
            act[p], wt + EO_WA[blk], bA[blk], nullptr,
            nullptr, nullptr, act[q], HDIM, EDIM + CDIM);
        // h2 = relu(h1 @ wB + bB) -> fp16
        gemm_f16<1, 1><<<dim3(NTOK / 64, HDIM / 256), 512, GEMM_SMEM>>>(
            act[q], wt + EO_WB[blk], bB[blk], nullptr,
            nullptr, nullptr, act[p], HDIM, HDIM);
        if (blk == 0) {
            // merged gates: N=2048 (delta|i), epilogue splits tanh/sigmoid
            gemm_f16<4, 0><<<dim3(NTOK / 64, 2048 / 256), 512, GEMM_SMEM>>>(
                act[p], wt + EO_GATE, db0, ib0,
                pdl, pig, nullptr, 2048, HDIM);
            ctx_update_kernel<<<NTOK, 256>>>(cg0, cb0);
        }
    }

    // logits = h2(block 1) @ ow + ob
    gemm_f16<0, 0><<<dim3(NTOK / 64, VDIM / 256), 512, GEMM_SMEM>>>(
        act[1], wt + EO_OW, ob, nullptr,
        out, nullptr, nullptr, VDIM, HDIM);
}